// round 8
// baseline (speedup 1.0000x reference)
#include <cuda_runtime.h>

// MaxPool2d: kernel=2, stride=2, padding=0
// Input:  (32, 64, 224, 224) fp32  -> NC = 2048 planes of 224x224
// Output: (32, 64, 112, 112) fp32
//
// R7: R6's fully-coalesced unit (thread loads consecutive-16B float4
//     from row 2oh and 2oh+1, emits float2) deepened to 4 warp-strided
//     units per thread -> 8 front-batched, perfectly-coalesced LDG.128
//     (MLP=8, 4 lines per load instruction) + 4 coalesced STG.64.
//     12,845,056 units == 12544 blocks * 1024. No tail.

#define IN_H    224
#define IN_W    224
#define OUT_H   112
#define OUT_W   112
#define NC      (32 * 64)

#define C4      (IN_W / 4)                  // 56 float4 chunks per input row
#define TOTAL   (NC * OUT_H * C4)           // 12,845,056 == 12544 * 1024

__device__ __forceinline__ void addrs(unsigned g,
                                      const float* __restrict__ in,
                                      float* __restrict__ out,
                                      const float** p, float** q)
{
    const unsigned c4  = g % C4;
    const unsigned tmp = g / C4;
    const unsigned oh  = tmp % OUT_H;
    const unsigned nc  = tmp / OUT_H;

    *p = in  + (size_t)nc * (IN_H * IN_W) + (size_t)(2u * oh) * IN_W + c4 * 4u;
    *q = out + (size_t)nc * (OUT_H * OUT_W) + (size_t)oh * OUT_W + c4 * 2u;
}

__global__ __launch_bounds__(256)
void maxpool2d_k2s2_kernel(const float* __restrict__ in,
                           float* __restrict__ out)
{
    const unsigned base = blockIdx.x * 1024u + threadIdx.x;

    const float *p0, *p1, *p2, *p3;
    float *q0, *q1, *q2, *q3;
    addrs(base,        in, out, &p0, &q0);
    addrs(base + 256u, in, out, &p1, &q1);
    addrs(base + 512u, in, out, &p2, &q2);
    addrs(base + 768u, in, out, &p3, &q3);

    // 8 independent, perfectly-coalesced LDG.128 (front-batched, MLP=8)
    const float4 a0 = *reinterpret_cast<const float4*>(p0);
    const float4 b0 = *reinterpret_cast<const float4*>(p0 + IN_W);
    const float4 a1 = *reinterpret_cast<const float4*>(p1);
    const float4 b1 = *reinterpret_cast<const float4*>(p1 + IN_W);
    const float4 a2 = *reinterpret_cast<const float4*>(p2);
    const float4 b2 = *reinterpret_cast<const float4*>(p2 + IN_W);
    const float4 a3 = *reinterpret_cast<const float4*>(p3);
    const float4 b3 = *reinterpret_cast<const float4*>(p3 + IN_W);

    float2 o0, o1, o2, o3;
    o0.x = fmaxf(fmaxf(a0.x, b0.x), fmaxf(a0.y, b0.y));
    o0.y = fmaxf(fmaxf(a0.z, b0.z), fmaxf(a0.w, b0.w));
    o1.x = fmaxf(fmaxf(a1.x, b1.x), fmaxf(a1.y, b1.y));
    o1.y = fmaxf(fmaxf(a1.z, b1.z), fmaxf(a1.w, b1.w));
    o2.x = fmaxf(fmaxf(a2.x, b2.x), fmaxf(a2.y, b2.y));
    o2.y = fmaxf(fmaxf(a2.z, b2.z), fmaxf(a2.w, b2.w));
    o3.x = fmaxf(fmaxf(a3.x, b3.x), fmaxf(a3.y, b3.y));
    o3.y = fmaxf(fmaxf(a3.z, b3.z), fmaxf(a3.w, b3.w));

    *reinterpret_cast<float2*>(q0) = o0;
    *reinterpret_cast<float2*>(q1) = o1;
    *reinterpret_cast<float2*>(q2) = o2;
    *reinterpret_cast<float2*>(q3) = o3;
}

extern "C" void kernel_launch(void* const* d_in, const int* in_sizes, int n_in,
                              void* d_out, int out_size)
{
    const float* x = (const float*)d_in[0];
    float* y = (float*)d_out;

    maxpool2d_k2s2_kernel<<<TOTAL / 1024, 256>>>(x, y);   // 12544 blocks, exact
}

// round 9
// speedup vs baseline: 1.0145x; 1.0145x over previous
#include <cuda_runtime.h>

// MaxPool2d: kernel=2, stride=2, padding=0
// Input:  (32, 64, 224, 224) fp32  -> NC = 2048 planes of 224x224
// Output: (32, 64, 112, 112) fp32
//
// FINAL (= R6, best measured: 75.5us wall, 86-88% DRAM, ~6.9 TB/s).
// Fully-coalesced-per-instruction layout:
//   Unit = (plane, output row, float4 column chunk): thread loads
//   in[2oh][4c4..4c4+4) and in[2oh+1][...] -- lanes hit CONSECUTIVE
//   16B (4 lines per LDG.128, minimal L1tex wavefronts), computes
//   vertical max then horizontal pair max -> float2 output (coalesced
//   8B stores). 2 warp-strided units per thread -> MLP=4.
//   12,845,056 units == 25088 blocks * 512. No tail, no guard.
//
// Exhausted-levers note: MLP {4,8,16}, lane-coalescing, cache hints,
// persistent grid, 64- vs 32-bit indexing all measured; everything sane
// lands in a 0.8us band at the HBM streaming ceiling. This config is
// the best of the band.

#define IN_H    224
#define IN_W    224
#define OUT_H   112
#define OUT_W   112
#define NC      (32 * 64)

#define C4      (IN_W / 4)                  // 56 float4 chunks per input row
#define TOTAL   (NC * OUT_H * C4)           // 12,845,056 == 25088 * 512

__device__ __forceinline__ void unit(unsigned g,
                                     const float* __restrict__ in,
                                     float* __restrict__ out)
{
    // 32-bit div/mod by constants -> magic-multiply IMADs
    const unsigned c4  = g % C4;
    const unsigned tmp = g / C4;
    const unsigned oh  = tmp % OUT_H;
    const unsigned nc  = tmp / OUT_H;

    const float* p = in + (size_t)nc * (IN_H * IN_W)
                        + (size_t)(2u * oh) * IN_W
                        + c4 * 4u;

    // Two fully-coalesced LDG.128 (lanes -> consecutive 16B)
    const float4 a = *reinterpret_cast<const float4*>(p);
    const float4 b = *reinterpret_cast<const float4*>(p + IN_W);

    // vertical max, then horizontal pair max -> 2 outputs
    float2 o;
    o.x = fmaxf(fmaxf(a.x, b.x), fmaxf(a.y, b.y));
    o.y = fmaxf(fmaxf(a.z, b.z), fmaxf(a.w, b.w));

    float* q = out + (size_t)nc * (OUT_H * OUT_W)
                   + (size_t)oh * OUT_W
                   + c4 * 2u;
    *reinterpret_cast<float2*>(q) = o;
}

__global__ __launch_bounds__(256)
void maxpool2d_k2s2_kernel(const float* __restrict__ in,
                           float* __restrict__ out)
{
    const unsigned base = blockIdx.x * 512u + threadIdx.x;
    // two warp-strided units -> 4 front-batched loads (MLP=4)
    unit(base,        in, out);
    unit(base + 256u, in, out);
}

extern "C" void kernel_launch(void* const* d_in, const int* in_sizes, int n_in,
                              void* d_out, int out_size)
{
    const float* x = (const float*)d_in[0];
    float* y = (float*)d_out;

    maxpool2d_k2s2_kernel<<<TOTAL / 512, 256>>>(x, y);   // 25088 blocks, exact
}